// round 2
// baseline (speedup 1.0000x reference)
#include <cuda_runtime.h>

#define NN 100000
#define HH 128
#define OO 64
#define GGmax 512
#define LGN 4

// ---------------- device scratch (no allocs allowed) ----------------
__device__ float g_pooled[(size_t)NN * HH];
__device__ float g_y1[(size_t)NN * HH];
__device__ float g_hA[(size_t)NN * HH];
__device__ float g_hB[(size_t)NN * HH];
__device__ float g_P[GGmax * HH];
__device__ float g_stats[2 * HH];   // [0:128) sum, [128:256) sumsq
__device__ float g_scale[HH];
__device__ float g_shift[HH];

// ---------------- helpers ----------------
__device__ __forceinline__ void fma2(unsigned long long& c, unsigned long long a, unsigned long long b) {
    asm("fma.rn.f32x2 %0, %1, %2, %0;" : "+l"(c) : "l"(a), "l"(b));
}
__device__ __forceinline__ float2 up2(unsigned long long v) {
    float2 f;
    asm("mov.b64 {%0,%1}, %2;" : "=f"(f.x), "=f"(f.y) : "l"(v));
    return f;
}
__device__ __forceinline__ void red_add_v4(float* p, float4 v) {
    asm volatile("red.global.add.v4.f32 [%0], {%1,%2,%3,%4};"
                 :: "l"(p), "f"(v.x), "f"(v.y), "f"(v.z), "f"(v.w) : "memory");
}

// ---------------- small kernels ----------------
// zero score output, g_P, g_stats in one launch
__global__ void k_init_misc(float* __restrict__ out, int nout, int np) {
    int i = blockIdx.x * blockDim.x + threadIdx.x;
    if (i < nout) out[i] = 0.0f;
    if (i < np) g_P[i] = 0.0f;
    if (i < 2 * HH) g_stats[i] = 0.0f;
}

// pooled = (1+eps[l]) * h   (layer 0 only; later layers fused into bnapply)
__global__ void k_init_pooled(const float* __restrict__ h, const float* __restrict__ eps, int n4) {
    int i = blockIdx.x * blockDim.x + threadIdx.x;
    if (i >= n4) return;
    float c = 1.0f + __ldg(eps);
    float4 v = ((const float4*)h)[i];
    v.x *= c; v.y *= c; v.z *= c; v.w *= c;
    ((float4*)g_pooled)[i] = v;
}

// pooled[dst[e]] += h[src[e]]   (1 warp per edge, red.v4 per lane)
__global__ void k_edges(const float* __restrict__ h, const int* __restrict__ src,
                        const int* __restrict__ dst, int e) {
    int t = blockIdx.x * blockDim.x + threadIdx.x;
    int edge = t >> 5;
    int lane = t & 31;
    if (edge >= e) return;
    int s = __ldg(src + edge);
    int d = __ldg(dst + edge);
    float4 v = ((const float4*)(h + (size_t)s * HH))[lane];
    red_add_v4(g_pooled + (size_t)d * HH + lane * 4, v);
}

// finalize BN from accumulated stats, then re-zero stats for next GEMM
__global__ void k_bnfin(const float* __restrict__ gamma, const float* __restrict__ beta,
                        int l, float inv_n) {
    int c = threadIdx.x;
    float m = g_stats[c] * inv_n;
    float v = g_stats[HH + c] * inv_n - m * m;
    float sc = __ldg(gamma + l * HH + c) * rsqrtf(v + 1e-5f);
    g_scale[c] = sc;
    g_shift[c] = __ldg(beta + l * HH + c) - m * sc;
    g_stats[c] = 0.0f;
    g_stats[HH + c] = 0.0f;
}

// h = relu(z*scale+shift); graph-pool into g_P; optionally write next pooled=(1+eps)*h
template <int WP>
__global__ void k_bnapply_pool(const float* __restrict__ Z, float* __restrict__ Hout,
                               const int* __restrict__ gid, const float* __restrict__ epsn,
                               int n4) {
    int i = blockIdx.x * blockDim.x + threadIdx.x;
    if (i >= n4) return;
    int node = i >> 5;
    int c4 = (i & 31) * 4;
    float4 v = ((const float4*)Z)[i];
    float4 sc = *(const float4*)&g_scale[c4];
    float4 sh = *(const float4*)&g_shift[c4];
    v.x = fmaxf(fmaf(v.x, sc.x, sh.x), 0.0f);
    v.y = fmaxf(fmaf(v.y, sc.y, sh.y), 0.0f);
    v.z = fmaxf(fmaf(v.z, sc.z, sh.z), 0.0f);
    v.w = fmaxf(fmaf(v.w, sc.w, sh.w), 0.0f);
    ((float4*)Hout)[i] = v;
    int g = __ldg(gid + node);
    red_add_v4(g_P + g * HH + c4, v);
    if (WP) {
        float c = 1.0f + __ldg(epsn);
        float4 p = make_float4(v.x * c, v.y * c, v.z * c, v.w * c);
        ((float4*)g_pooled)[i] = p;
    }
}

// graph sum pool of raw x (layer-0 head)
__global__ void k_pool(const float* __restrict__ h, const int* __restrict__ gid, int n) {
    int t = blockIdx.x * blockDim.x + threadIdx.x;
    int node = t >> 5;
    int lane = t & 31;
    if (node >= n) return;
    int g = __ldg(gid + node);
    float4 v = ((const float4*)(h + (size_t)node * HH))[lane];
    red_add_v4(g_P + g * HH + lane * 4, v);
}

// score[g] += P[g] @ Wp[l] + bp[l]; then re-zero P slice for next layer
__global__ void k_score(const float* __restrict__ Wp, const float* __restrict__ bp,
                        int l, float* __restrict__ out) {
    __shared__ float Pg[HH];
    int g = blockIdx.x;
    int t = threadIdx.x;  // 64
    Pg[t]      = g_P[g * HH + t];
    Pg[t + 64] = g_P[g * HH + t + 64];
    __syncthreads();
    g_P[g * HH + t] = 0.0f;
    g_P[g * HH + t + 64] = 0.0f;
    const float* w = Wp + (size_t)l * HH * OO;
    float acc = __ldg(bp + l * OO + t);
    #pragma unroll
    for (int k = 0; k < HH; k++) acc = fmaf(Pg[k], __ldg(w + k * OO + t), acc);
    out[g * OO + t] += acc;
}

// ---------------- tiled fp32 GEMM: C = op(A) @ W + bias, + column stats ----------------
// A: n x 128 row-major, W: 128 x 128 row-major. 128-row tile, 256 threads, 8x8/thread.
// f32x2 packed accumulators with zero packing MOVs:
//   A stored duplicated {a,a} in smem -> LDS gives packed-duplicated operand;
//   B read as natural adjacent pairs {b_j,b_j+1}.
// BN_A=1: relu(a*g_scale+g_shift) fused into A-tile load.
// Epilogue: per-column sum/sumsq reduced in smem, atomically added to g_stats.
#define WST 132
#define AST 260
#define GEMM_SMEM ((128 * WST + 8 * AST) * 4)

template <int BN_A>
__global__ void __launch_bounds__(256, 2) k_gemm(const float* __restrict__ A,
                                                 const float* __restrict__ W,
                                                 const float* __restrict__ bias,
                                                 float* __restrict__ C, int n) {
    extern __shared__ float smem[];
    float* Ws  = smem;                // [128][WST]
    float* As2 = smem + 128 * WST;    // [8][AST] duplicated: As2[k][2r]=As2[k][2r+1]=a(r,k)

    int tid = threadIdx.x;
    int tx = tid & 15;       // 16 col-groups of 8
    int ty = tid >> 4;       // 16 row-groups of 8
    int quad = tid & 1;      // A-load: which half of 8 k's
    int rl = tid >> 1;       // A-load: local row 0..127

    for (int i = tid; i < 128 * 32; i += 256) {
        int k = i >> 5;
        int c = (i & 31) * 4;
        *(float4*)&Ws[k * WST + c] = ((const float4*)W)[i];
    }

    long rowBase = (long)blockIdx.x * 128;
    unsigned long long acc[8][4];  // [row i][col-pair jp] = {c(i,2jp), c(i,2jp+1)}
    #pragma unroll
    for (int i = 0; i < 8; i++)
        #pragma unroll
        for (int j = 0; j < 4; j++) acc[i][j] = 0ull;

    for (int kk = 0; kk < 128; kk += 8) {
        __syncthreads();
        long row = rowBase + rl;
        float4 a4 = make_float4(0.f, 0.f, 0.f, 0.f);
        if (row < n) a4 = *(const float4*)(A + row * HH + kk + quad * 4);
        if (BN_A) {
            int kb = kk + quad * 4;
            a4.x = fmaxf(fmaf(a4.x, g_scale[kb + 0], g_shift[kb + 0]), 0.0f);
            a4.y = fmaxf(fmaf(a4.y, g_scale[kb + 1], g_shift[kb + 1]), 0.0f);
            a4.z = fmaxf(fmaf(a4.z, g_scale[kb + 2], g_shift[kb + 2]), 0.0f);
            a4.w = fmaxf(fmaf(a4.w, g_scale[kb + 3], g_shift[kb + 3]), 0.0f);
        }
        float av[4] = {a4.x, a4.y, a4.z, a4.w};
        #pragma unroll
        for (int j = 0; j < 4; j++)
            *(float2*)&As2[(quad * 4 + j) * AST + 2 * rl] = make_float2(av[j], av[j]);
        __syncthreads();

        #pragma unroll
        for (int k8 = 0; k8 < 8; k8++) {
            int k = kk + k8;
            ulonglong2 b01 = *(ulonglong2*)&Ws[k * WST + tx * 8];      // {b0,b1},{b2,b3}
            ulonglong2 b45 = *(ulonglong2*)&Ws[k * WST + tx * 8 + 4];  // {b4,b5},{b6,b7}
            ulonglong2 aA = *(ulonglong2*)&As2[k8 * AST + ty * 16];       // rows 0,1 dup
            ulonglong2 aB = *(ulonglong2*)&As2[k8 * AST + ty * 16 + 4];   // rows 2,3
            ulonglong2 aC = *(ulonglong2*)&As2[k8 * AST + ty * 16 + 8];   // rows 4,5
            ulonglong2 aD = *(ulonglong2*)&As2[k8 * AST + ty * 16 + 12];  // rows 6,7
            unsigned long long av8[8] = {aA.x, aA.y, aB.x, aB.y, aC.x, aC.y, aD.x, aD.y};
            #pragma unroll
            for (int i = 0; i < 8; i++) {
                fma2(acc[i][0], av8[i], b01.x);
                fma2(acc[i][1], av8[i], b01.y);
                fma2(acc[i][2], av8[i], b45.x);
                fma2(acc[i][3], av8[i], b45.y);
            }
        }
    }

    float bc[8];
    #pragma unroll
    for (int j = 0; j < 8; j++) bc[j] = __ldg(bias + tx * 8 + j);

    float cs[8], cq[8];
    #pragma unroll
    for (int j = 0; j < 8; j++) { cs[j] = 0.0f; cq[j] = 0.0f; }

    #pragma unroll
    for (int i = 0; i < 8; i++) {
        long row = rowBase + ty * 8 + i;
        if (row < n) {
            float2 p0 = up2(acc[i][0]);
            float2 p1 = up2(acc[i][1]);
            float2 p2 = up2(acc[i][2]);
            float2 p3 = up2(acc[i][3]);
            float o[8] = {p0.x + bc[0], p0.y + bc[1], p1.x + bc[2], p1.y + bc[3],
                          p2.x + bc[4], p2.y + bc[5], p3.x + bc[6], p3.y + bc[7]};
            *(float4*)(C + row * HH + tx * 8)     = make_float4(o[0], o[1], o[2], o[3]);
            *(float4*)(C + row * HH + tx * 8 + 4) = make_float4(o[4], o[5], o[6], o[7]);
            #pragma unroll
            for (int j = 0; j < 8; j++) { cs[j] += o[j]; cq[j] = fmaf(o[j], o[j], cq[j]); }
        }
    }

    // column-stats block reduction (reuse smem; all compute done)
    __syncthreads();
    float* sm_s = smem;          // [128][16]
    float* sm_q = smem + 2048;   // [128][16]
    #pragma unroll
    for (int j = 0; j < 8; j++) {
        sm_s[(tx * 8 + j) * 16 + ty] = cs[j];
        sm_q[(tx * 8 + j) * 16 + ty] = cq[j];
    }
    __syncthreads();
    if (tid < 128) {
        float S = 0.0f, Q = 0.0f;
        #pragma unroll
        for (int t2 = 0; t2 < 16; t2++) { S += sm_s[tid * 16 + t2]; Q += sm_q[tid * 16 + t2]; }
        atomicAdd(&g_stats[tid], S);
        atomicAdd(&g_stats[HH + tid], Q);
    }
}

// ---------------- host orchestration ----------------
extern "C" void kernel_launch(void* const* d_in, const int* in_sizes, int n_in,
                              void* d_out, int out_size) {
    const float* x   = (const float*)d_in[0];
    const int*   src = (const int*)d_in[1];
    const int*   dst = (const int*)d_in[2];
    const int*   gid = (const int*)d_in[3];
    // d_in[4] = num_graphs (device scalar; G implied by out_size)
    const float* eps = (const float*)d_in[5];
    const float* W1  = (const float*)d_in[6];
    const float* b1  = (const float*)d_in[7];
    const float* gm  = (const float*)d_in[8];
    const float* bm  = (const float*)d_in[9];
    const float* W2  = (const float*)d_in[10];
    const float* b2  = (const float*)d_in[11];
    const float* go  = (const float*)d_in[12];
    const float* bo  = (const float*)d_in[13];
    const float* Wp  = (const float*)d_in[14];
    const float* bp  = (const float*)d_in[15];
    float* out = (float*)d_out;

    int n = in_sizes[0] / HH;
    int e = in_sizes[1];
    int g = out_size / OO;
    int n4 = n * (HH / 4);

    float *pPooled, *pY1, *pHA, *pHB;
    cudaGetSymbolAddress((void**)&pPooled, g_pooled);
    cudaGetSymbolAddress((void**)&pY1, g_y1);
    cudaGetSymbolAddress((void**)&pHA, g_hA);
    cudaGetSymbolAddress((void**)&pHB, g_hB);

    cudaFuncSetAttribute(k_gemm<0>, cudaFuncAttributeMaxDynamicSharedMemorySize, GEMM_SMEM);
    cudaFuncSetAttribute(k_gemm<1>, cudaFuncAttributeMaxDynamicSharedMemorySize, GEMM_SMEM);

    const int TB = 256;
    int gemm_grid = (n + 127) / 128;
    float inv_n = 1.0f / (float)n;

    // zero score/P/stats in one launch
    int ninit = (g * HH > g * OO) ? g * HH : g * OO;
    k_init_misc<<<(ninit + TB - 1) / TB, TB>>>(out, g * OO, g * HH);

    // layer-0 head on raw x (k_score re-zeroes P afterwards)
    k_pool<<<((long)n * 32 + TB - 1) / TB, TB>>>(x, gid, n);
    k_score<<<g, OO>>>(Wp, bp, 0, out);

    const float* hin = x;
    float* houts[LGN] = {pHA, pHB, pHA, pHB};

    for (int l = 0; l < LGN; l++) {
        if (l == 0)
            k_init_pooled<<<(n4 + TB - 1) / TB, TB>>>(x, eps, n4);
        // pooled += neighbor sum
        k_edges<<<((long)e * 32 + TB - 1) / TB, TB>>>(hin, src, dst, e);

        // y1 = pooled @ W1 + b1  (+ BN1 stats)
        k_gemm<0><<<gemm_grid, TB, GEMM_SMEM>>>(pPooled, W1 + (size_t)l * HH * HH,
                                                b1 + l * HH, pY1, n);
        k_bnfin<<<1, HH>>>(gm, bm, l, inv_n);

        // z = relu(BN1(y1)) @ W2 + b2 -> g_pooled  (+ BN2 stats)
        k_gemm<1><<<gemm_grid, TB, GEMM_SMEM>>>(pY1, W2 + (size_t)l * HH * HH,
                                                b2 + l * HH, pPooled, n);
        k_bnfin<<<1, HH>>>(go, bo, l, inv_n);

        // h = relu(BN2(z)); pool into P; write next pooled=(1+eps)*h if not last layer
        float* hout = houts[l];
        if (l + 1 < LGN)
            k_bnapply_pool<1><<<(n4 + TB - 1) / TB, TB>>>(pPooled, hout, gid, eps + l + 1, n4);
        else
            k_bnapply_pool<0><<<(n4 + TB - 1) / TB, TB>>>(pPooled, hout, gid, eps, n4);

        // per-layer head (also re-zeroes P)
        k_score<<<g, OO>>>(Wp, bp, l + 1, out);

        hin = hout;
    }
}

// round 14
// speedup vs baseline: 1.0085x; 1.0085x over previous
#include <cuda_runtime.h>
#include <cuda_bf16.h>
#include <cstdint>

#define NN 100000
#define EE 1600512
#define HH 128
#define OO 64
#define GGmax 512
#define LGN 4

// ---------------- device scratch (no allocs allowed) ----------------
__device__ float g_pooled[(size_t)NN * HH];
__device__ float g_y1[(size_t)NN * HH];
__device__ float g_hA[(size_t)NN * HH];
__device__ float g_hB[(size_t)NN * HH];
__device__ float g_P[GGmax * HH];
__device__ float g_stats[2 * HH];   // [0:128) sum, [128:256) sumsq
__device__ float g_scale[HH];
__device__ float g_shift[HH];
// W in mma B-fragment order: [mat 0..7=l*2+m][split hi/lo][ktile*16+ntile][lane] uint2
__device__ uint2 g_Wf[8 * 2 * 128 * 32];
// CSR-by-dst (built once per call, reused across layers)
__device__ int g_cnt[NN];
__device__ int g_rowptr[NN + 1];
__device__ int g_cursor[NN];
__device__ int g_esrc[EE];

// ---------------- helpers ----------------
__device__ __forceinline__ float bf16f(float x) {
    return __bfloat162float(__float2bfloat16(x));
}
__device__ __forceinline__ uint32_t pkbf(float x, float y) {
    __nv_bfloat162 t = __floats2bfloat162_rn(x, y);
    return *(uint32_t*)&t;
}
__device__ __forceinline__ void red_add_v4(float* p, float4 v) {
    asm volatile("red.global.add.v4.f32 [%0], {%1,%2,%3,%4};"
                 :: "l"(p), "f"(v.x), "f"(v.y), "f"(v.z), "f"(v.w) : "memory");
}
__device__ __forceinline__ void red_add_f(float* p, float v) {
    asm volatile("red.global.add.f32 [%0], %1;" :: "l"(p), "f"(v) : "memory");
}
__device__ __forceinline__ void mma_bf16(float* d, const uint32_t* a, const uint32_t* b) {
    asm volatile(
        "mma.sync.aligned.m16n8k16.row.col.f32.bf16.bf16.f32 "
        "{%0,%1,%2,%3}, {%4,%5,%6,%7}, {%8,%9}, {%0,%1,%2,%3};"
        : "+f"(d[0]), "+f"(d[1]), "+f"(d[2]), "+f"(d[3])
        : "r"(a[0]), "r"(a[1]), "r"(a[2]), "r"(a[3]), "r"(b[0]), "r"(b[1]));
}

// ---------------- CSR build ----------------
__global__ void k_czero(int n) {
    int i = blockIdx.x * blockDim.x + threadIdx.x;
    if (i < n) g_cnt[i] = 0;
}
__global__ void k_ccount(const int* __restrict__ dst, int e) {
    int i = blockIdx.x * blockDim.x + threadIdx.x;
    if (i < e) atomicAdd(&g_cnt[__ldg(dst + i)], 1);
}
// single-block exclusive scan of g_cnt -> g_rowptr/g_cursor; g_rowptr[n] = e
__global__ void k_cscan(int n, int e) {
    __shared__ int bs[1024];
    int tid = threadIdx.x;
    int per = (n + 1023) >> 10;
    int lo = tid * per;
    int hi = min(n, lo + per);
    int s = 0;
    for (int i = lo; i < hi; i++) s += g_cnt[i];
    bs[tid] = s;
    __syncthreads();
    // inclusive Hillis-Steele scan
    for (int d = 1; d < 1024; d <<= 1) {
        int v = (tid >= d) ? bs[tid - d] : 0;
        __syncthreads();
        bs[tid] += v;
        __syncthreads();
    }
    int run = bs[tid] - s;  // exclusive prefix for this thread's chunk
    for (int i = lo; i < hi; i++) {
        g_rowptr[i] = run;
        g_cursor[i] = run;
        run += g_cnt[i];
    }
    if (tid == 0) g_rowptr[n] = e;
}
__global__ void k_cscatter(const int* __restrict__ src, const int* __restrict__ dst, int e) {
    int i = blockIdx.x * blockDim.x + threadIdx.x;
    if (i >= e) return;
    int pos = atomicAdd(&g_cursor[__ldg(dst + i)], 1);
    g_esrc[pos] = __ldg(src + i);
}

// ---------------- gather aggregation: pooled = (1+eps)*h[node] + sum h[src] ----
__global__ void k_gather(const float* __restrict__ h, const float* __restrict__ eps,
                         int l, int n) {
    int t = blockIdx.x * blockDim.x + threadIdx.x;
    int node = t >> 5;
    int lane = t & 31;
    if (node >= n) return;
    float c = 1.0f + __ldg(eps + l);
    const float4* hv = (const float4*)h;
    float4 a = __ldg(hv + (size_t)node * 32 + lane);
    float4 acc = make_float4(a.x * c, a.y * c, a.z * c, a.w * c);
    int j = __ldg(&g_rowptr[node]);
    int end = __ldg(&g_rowptr[node + 1]);
    // 4-wide unroll: 4 independent LDG.128 in flight per iteration
    for (; j + 3 < end; j += 4) {
        int s0 = __ldg(&g_esrc[j]);
        int s1 = __ldg(&g_esrc[j + 1]);
        int s2 = __ldg(&g_esrc[j + 2]);
        int s3 = __ldg(&g_esrc[j + 3]);
        float4 v0 = __ldg(hv + (size_t)s0 * 32 + lane);
        float4 v1 = __ldg(hv + (size_t)s1 * 32 + lane);
        float4 v2 = __ldg(hv + (size_t)s2 * 32 + lane);
        float4 v3 = __ldg(hv + (size_t)s3 * 32 + lane);
        acc.x += (v0.x + v1.x) + (v2.x + v3.x);
        acc.y += (v0.y + v1.y) + (v2.y + v3.y);
        acc.z += (v0.z + v1.z) + (v2.z + v3.z);
        acc.w += (v0.w + v1.w) + (v2.w + v3.w);
    }
    for (; j < end; j++) {
        int s0 = __ldg(&g_esrc[j]);
        float4 v0 = __ldg(hv + (size_t)s0 * 32 + lane);
        acc.x += v0.x; acc.y += v0.y; acc.z += v0.z; acc.w += v0.w;
    }
    ((float4*)g_pooled)[(size_t)node * 32 + lane] = acc;
}

// ---------------- small kernels ----------------
__global__ void k_init_misc(float* __restrict__ out, int nout, int np) {
    int i = blockIdx.x * blockDim.x + threadIdx.x;
    if (i < nout) out[i] = 0.0f;
    if (i < np) g_P[i] = 0.0f;
    if (i < 2 * HH) g_stats[i] = 0.0f;
}

// Build W fragment tables (hi/lo bf16 splits) in mma B-fragment layout.
// B frag (m16n8k16, col): b0={W[k0][n],W[k0+1][n]}, b1={W[k0+8][n],W[k0+9][n]},
// k0 = 16*t + 2*(lane&3), n = 8*u + (lane>>2).
__global__ void k_wprep(const float* __restrict__ W1, const float* __restrict__ W2) {
    int i = blockIdx.x * blockDim.x + threadIdx.x;  // 8 mats * 128 tiles * 32 lanes
    if (i >= 8 * 128 * 32) return;
    int lane = i & 31;
    int tile = (i >> 5) & 127;
    int mat = i >> 12;
    int t = tile >> 4, u = tile & 15;
    int l = mat >> 1, m = mat & 1;
    const float* W = (m ? W2 : W1) + (size_t)l * 16384;
    int k0 = 16 * t + 2 * (lane & 3);
    int nn = 8 * u + (lane >> 2);
    float w00 = __ldg(W + k0 * HH + nn);
    float w01 = __ldg(W + (k0 + 1) * HH + nn);
    float w10 = __ldg(W + (k0 + 8) * HH + nn);
    float w11 = __ldg(W + (k0 + 9) * HH + nn);
    uint2 hi, lo;
    hi.x = pkbf(w00, w01);
    hi.y = pkbf(w10, w11);
    lo.x = pkbf(w00 - bf16f(w00), w01 - bf16f(w01));
    lo.y = pkbf(w10 - bf16f(w10), w11 - bf16f(w11));
    g_Wf[((size_t)(mat * 2 + 0) * 128 + tile) * 32 + lane] = hi;
    g_Wf[((size_t)(mat * 2 + 1) * 128 + tile) * 32 + lane] = lo;
}

__global__ void k_bnfin(const float* __restrict__ gamma, const float* __restrict__ beta,
                        int l, float inv_n) {
    int c = threadIdx.x;
    float m = g_stats[c] * inv_n;
    float v = g_stats[HH + c] * inv_n - m * m;
    float sc = __ldg(gamma + l * HH + c) * rsqrtf(v + 1e-5f);
    g_scale[c] = sc;
    g_shift[c] = __ldg(beta + l * HH + c) - m * sc;
    g_stats[c] = 0.0f;
    g_stats[HH + c] = 0.0f;
}

// h = relu(z*scale+shift); graph-pool into g_P
__global__ void k_bnapply_pool(const float* __restrict__ Z, float* __restrict__ Hout,
                               const int* __restrict__ gid, int n4) {
    int i = blockIdx.x * blockDim.x + threadIdx.x;
    if (i >= n4) return;
    int node = i >> 5;
    int c4 = (i & 31) * 4;
    float4 v = ((const float4*)Z)[i];
    float4 sc = *(const float4*)&g_scale[c4];
    float4 sh = *(const float4*)&g_shift[c4];
    v.x = fmaxf(fmaf(v.x, sc.x, sh.x), 0.0f);
    v.y = fmaxf(fmaf(v.y, sc.y, sh.y), 0.0f);
    v.z = fmaxf(fmaf(v.z, sc.z, sh.z), 0.0f);
    v.w = fmaxf(fmaf(v.w, sc.w, sh.w), 0.0f);
    ((float4*)Hout)[i] = v;
    int g = __ldg(gid + node);
    red_add_v4(g_P + g * HH + c4, v);
}

__global__ void k_pool(const float* __restrict__ h, const int* __restrict__ gid, int n) {
    int t = blockIdx.x * blockDim.x + threadIdx.x;
    int node = t >> 5;
    int lane = t & 31;
    if (node >= n) return;
    int g = __ldg(gid + node);
    float4 v = ((const float4*)(h + (size_t)node * HH))[lane];
    red_add_v4(g_P + g * HH + lane * 4, v);
}

__global__ void k_score(const float* __restrict__ Wp, const float* __restrict__ bp,
                        int l, float* __restrict__ out) {
    __shared__ float Pg[HH];
    int g = blockIdx.x;
    int t = threadIdx.x;  // 64
    Pg[t]      = g_P[g * HH + t];
    Pg[t + 64] = g_P[g * HH + t + 64];
    __syncthreads();
    g_P[g * HH + t] = 0.0f;
    g_P[g * HH + t + 64] = 0.0f;
    const float* w = Wp + (size_t)l * HH * OO;
    float acc = __ldg(bp + l * OO + t);
    #pragma unroll
    for (int k = 0; k < HH; k++) acc = fmaf(Pg[k], __ldg(w + k * OO + t), acc);
    out[g * OO + t] += acc;
}

// ---------------- HMMA bf16 3-split GEMM: C = op(A) @ W + bias, + col stats ----
// 128 rows/CTA, 256 threads (8 warps x 16 rows). A fp32 -> hi/lo bf16 fragments
// in registers (BN+ReLU fused when BN_A). W fragments staged smem (64KB).
// acc fp32 via mma.sync m16n8k16: Ah*Wh + Ah*Wl + Al*Wh.
#define GEMM_SMEM_MMA 65536

template <int BN_A>
__global__ void __launch_bounds__(256, 2) k_gemm_mma(const float* __restrict__ A,
                                                     const uint2* __restrict__ Wf,
                                                     const float* __restrict__ bias,
                                                     float* __restrict__ C, int n) {
    extern __shared__ uint2 swf[];  // hi frags [0,4096), lo frags [4096,8192)
    int tid = threadIdx.x;
    int lane = tid & 31;
    int w = tid >> 5;

    // stage FULL table: 8192 uint2 = 4096 uint4 (hi AND lo splits)
    for (int i = tid; i < 4096; i += 256)
        ((uint4*)swf)[i] = __ldg((const uint4*)Wf + i);
    __syncthreads();

    int q = lane & 3;
    int g = lane >> 2;
    long r0 = (long)blockIdx.x * 128 + w * 16 + g;
    long r1 = r0 + 8;
    bool act0 = r0 < n, act1 = r1 < n;
    const float* A0 = A + r0 * HH;
    const float* A1 = A + r1 * HH;

    float acc[16][4];
    #pragma unroll
    for (int u = 0; u < 16; u++)
        #pragma unroll
        for (int j = 0; j < 4; j++) acc[u][j] = 0.0f;

    for (int t = 0; t < 8; t++) {
        int c0 = 16 * t + 2 * q;
        int c1 = c0 + 8;
        float2 z2 = make_float2(0.f, 0.f);
        float2 x00 = act0 ? __ldg((const float2*)(A0 + c0)) : z2;
        float2 x01 = act0 ? __ldg((const float2*)(A0 + c1)) : z2;
        float2 x10 = act1 ? __ldg((const float2*)(A1 + c0)) : z2;
        float2 x11 = act1 ? __ldg((const float2*)(A1 + c1)) : z2;
        if (BN_A) {
            float2 sc0 = *(const float2*)&g_scale[c0];
            float2 sh0 = *(const float2*)&g_shift[c0];
            float2 sc1 = *(const float2*)&g_scale[c1];
            float2 sh1 = *(const float2*)&g_shift[c1];
            x00.x = fmaxf(fmaf(x00.x, sc0.x, sh0.x), 0.0f);
            x00.y = fmaxf(fmaf(x00.y, sc0.y, sh0.y), 0.0f);
            x10.x = fmaxf(fmaf(x10.x, sc0.x, sh0.x), 0.0f);
            x10.y = fmaxf(fmaf(x10.y, sc0.y, sh0.y), 0.0f);
            x01.x = fmaxf(fmaf(x01.x, sc1.x, sh1.x), 0.0f);
            x01.y = fmaxf(fmaf(x01.y, sc1.y, sh1.y), 0.0f);
            x11.x = fmaxf(fmaf(x11.x, sc1.x, sh1.x), 0.0f);
            x11.y = fmaxf(fmaf(x11.y, sc1.y, sh1.y), 0.0f);
            if (!act0) { x00 = z2; x01 = z2; }
            if (!act1) { x10 = z2; x11 = z2; }
        }
        uint32_t ah[4], al[4];
        ah[0] = pkbf(x00.x, x00.y);
        ah[1] = pkbf(x10.x, x10.y);
        ah[2] = pkbf(x01.x, x01.y);
        ah[3] = pkbf(x11.x, x11.y);
        al[0] = pkbf(x00.x - bf16f(x00.x), x00.y - bf16f(x00.y));
        al[1] = pkbf(x10.x - bf16f(x10.x), x10.y - bf16f(x10.y));
        al[2] = pkbf(x01.x - bf16f(x01.x), x01.y - bf16f(x01.y));
        al[3] = pkbf(x11.x - bf16f(x11.x), x11.y - bf16f(x11.y));

        #pragma unroll
        for (int u = 0; u < 16; u++) {
            int fi = (t * 16 + u) * 32 + lane;
            uint2 bh = swf[fi];
            uint2 bl = swf[4096 + fi];
            mma_bf16(acc[u], ah, (const uint32_t*)&bh);
            mma_bf16(acc[u], ah, (const uint32_t*)&bl);
            mma_bf16(acc[u], al, (const uint32_t*)&bh);
        }
    }

    // epilogue: bias, store, column stats
    #pragma unroll
    for (int u = 0; u < 16; u++) {
        int nb = 8 * u + 2 * q;
        float2 bs = __ldg((const float2*)(bias + nb));
        float o0 = acc[u][0] + bs.x, o1 = acc[u][1] + bs.y;  // row r0
        float o2 = acc[u][2] + bs.x, o3 = acc[u][3] + bs.y;  // row r1
        if (!act0) { o0 = 0.0f; o1 = 0.0f; }
        if (!act1) { o2 = 0.0f; o3 = 0.0f; }
        if (act0) *(float2*)(C + r0 * HH + nb) = make_float2(o0, o1);
        if (act1) *(float2*)(C + r1 * HH + nb) = make_float2(o2, o3);
        float s0 = o0 + o2, s1 = o1 + o3;
        float q0 = o0 * o0 + o2 * o2, q1 = o1 * o1 + o3 * o3;
        #pragma unroll
        for (int off = 4; off < 32; off <<= 1) {
            s0 += __shfl_xor_sync(0xFFFFFFFFu, s0, off);
            s1 += __shfl_xor_sync(0xFFFFFFFFu, s1, off);
            q0 += __shfl_xor_sync(0xFFFFFFFFu, q0, off);
            q1 += __shfl_xor_sync(0xFFFFFFFFu, q1, off);
        }
        if (lane < 4) {
            red_add_f(&g_stats[nb], s0);
            red_add_f(&g_stats[nb + 1], s1);
            red_add_f(&g_stats[HH + nb], q0);
            red_add_f(&g_stats[HH + nb + 1], q1);
        }
    }
}

// ---------------- host orchestration ----------------
extern "C" void kernel_launch(void* const* d_in, const int* in_sizes, int n_in,
                              void* d_out, int out_size) {
    const float* x   = (const float*)d_in[0];
    const int*   src = (const int*)d_in[1];
    const int*   dst = (const int*)d_in[2];
    const int*   gid = (const int*)d_in[3];
    const float* eps = (const float*)d_in[5];
    const float* W1  = (const float*)d_in[6];
    const float* b1  = (const float*)d_in[7];
    const float* gm  = (const float*)d_in[8];
    const float* bm  = (const float*)d_in[9];
    const float* W2  = (const float*)d_in[10];
    const float* b2  = (const float*)d_in[11];
    const float* go  = (const float*)d_in[12];
    const float* bo  = (const float*)d_in[13];
    const float* Wp  = (const float*)d_in[14];
    const float* bp  = (const float*)d_in[15];
    float* out = (float*)d_out;

    int n = in_sizes[0] / HH;
    int e = in_sizes[1];
    int g = out_size / OO;
    int n4 = n * (HH / 4);

    float *pPooled, *pY1, *pHA, *pHB;
    uint2* pWf;
    cudaGetSymbolAddress((void**)&pPooled, g_pooled);
    cudaGetSymbolAddress((void**)&pY1, g_y1);
    cudaGetSymbolAddress((void**)&pHA, g_hA);
    cudaGetSymbolAddress((void**)&pHB, g_hB);
    cudaGetSymbolAddress((void**)&pWf, g_Wf);

    cudaFuncSetAttribute(k_gemm_mma<0>, cudaFuncAttributeMaxDynamicSharedMemorySize, GEMM_SMEM_MMA);
    cudaFuncSetAttribute(k_gemm_mma<1>, cudaFuncAttributeMaxDynamicSharedMemorySize, GEMM_SMEM_MMA);

    const int TB = 256;
    int gemm_grid = (n + 127) / 128;
    float inv_n = 1.0f / (float)n;

    // CSR build (once per call; graph shared across layers)
    k_czero<<<(n + TB - 1) / TB, TB>>>(n);
    k_ccount<<<(e + TB - 1) / TB, TB>>>(dst, e);
    k_cscan<<<1, 1024>>>(n, e);
    k_cscatter<<<(e + TB - 1) / TB, TB>>>(src, dst, e);

    int ninit = (g * HH > g * OO) ? g * HH : g * OO;
    k_init_misc<<<(ninit + TB - 1) / TB, TB>>>(out, g * OO, g * HH);
    k_wprep<<<128, 256>>>(W1, W2);

    // layer-0 head on raw x
    k_pool<<<((long)n * 32 + TB - 1) / TB, TB>>>(x, gid, n);
    k_score<<<g, OO>>>(Wp, bp, 0, out);

    const float* hin = x;
    float* houts[LGN] = {pHA, pHB, pHA, pHB};

    for (int l = 0; l < LGN; l++) {
        // pooled = (1+eps)*h + neighbor-sum (gather, no atomics)
        k_gather<<<((long)n * 32 + TB - 1) / TB, TB>>>(hin, eps, l, n);

        // y1 = pooled @ W1 + b1 (+ BN1 stats)
        k_gemm_mma<0><<<gemm_grid, TB, GEMM_SMEM_MMA>>>(
            pPooled, pWf + (size_t)(l * 2 + 0) * 2 * 4096, b1 + l * HH, pY1, n);
        k_bnfin<<<1, HH>>>(gm, bm, l, inv_n);

        // z = relu(BN1(y1)) @ W2 + b2 -> g_pooled (+ BN2 stats)
        k_gemm_mma<1><<<gemm_grid, TB, GEMM_SMEM_MMA>>>(
            pY1, pWf + (size_t)(l * 2 + 1) * 2 * 4096, b2 + l * HH, pPooled, n);
        k_bnfin<<<1, HH>>>(go, bo, l, inv_n);

        float* hout = houts[l];
        k_bnapply_pool<<<(n4 + TB - 1) / TB, TB>>>(pPooled, hout, gid, n4);

        k_score<<<g, OO>>>(Wp, bp, l + 1, out);
        hin = hout;
    }
}